// round 5
// baseline (speedup 1.0000x reference)
#include <cuda_runtime.h>
#include <cuda_bf16.h>

// Problem constants (fixed by the reference)
#define N_NODES 8192
#define K_NB    64
#define F_DIM   128
#define ROW_LEN 257                         // 2F+1
#define TOTAL_E (N_NODES * K_NB)            // 524288 write events
#define SAMPLES_ELEMS ((long long)TOTAL_E * ROW_LEN)
#define TILE_R   128                        // rows per fill tile
#define N_TILES  (N_NODES / TILE_R)         // 64
#define CAP      16                         // per-(col,tile) bucket cap (Poisson(1))
#define NB       (N_NODES * N_TILES)        // 524288 micro-buckets
#define FILL_BLKS 256                       // 64 row-tiles * 4 col-blocks (8 cols/thread)

// Scratch (allocation-free __device__ globals)
__device__ int g_cnt[NB];                   // 2 MB  events per (col,tile)
__device__ int g_bkt[NB * CAP];             // 32 MB timestamps
__device__ int g_carry[NB];                 // 2 MB  max ts in tiles < t (-1 if none)

__device__ __forceinline__ void stg256(float* p, const float* v) {
    asm volatile("st.global.v8.f32 [%0], {%1,%2,%3,%4,%5,%6,%7,%8};"
                 :: "l"(p), "f"(v[0]), "f"(v[1]), "f"(v[2]), "f"(v[3]),
                    "f"(v[4]), "f"(v[5]), "f"(v[6]), "f"(v[7]) : "memory");
}

// ---------------------------------------------------------------------------
__global__ void zero_kernel() {
    ((int4*)g_cnt)[blockIdx.x * blockDim.x + threadIdx.x] = make_int4(0, 0, 0, 0);
}

// Scatter each event ts = r*K+j into micro-bucket (col, r/TILE_R).
__global__ void scatter_kernel(const int* __restrict__ idx_in) {
    const int e = blockIdx.x * blockDim.x + threadIdx.x;
    const int r = e >> 6;
    const int j = e & (K_NB - 1);
    const int c = (j < K_NB - 1) ? __ldg(&idx_in[r * (K_NB - 1) + j]) : r;
    const int bid = c * N_TILES + (r >> 7);
    const int p = atomicAdd(&g_cnt[bid], 1);
    if (p < CAP) g_bkt[bid * CAP + p] = e;
}

// Warp per column: sort each micro-bucket (mean 1 event), then exclusive
// prefix-max of bucket maxima over the 64 tiles -> carry-in timestamps.
__device__ __forceinline__ int sort_bucket(int b) {
    int m = g_cnt[b]; if (m > CAP) m = CAP;
    int* __restrict__ a = &g_bkt[b * CAP];
    for (int i = 1; i < m; i++) {
        int v = a[i], j = i - 1;
        while (j >= 0 && a[j] > v) { a[j + 1] = a[j]; j--; }
        a[j + 1] = v;
    }
    return (m > 0) ? a[m - 1] : -1;          // bucket max ts (sorted => last)
}

__global__ void sortcarry_kernel() {
    const int c    = blockIdx.x * 8 + (threadIdx.x >> 5);
    const int lane = threadIdx.x & 31;
    const int base = c * N_TILES;
    const int b0 = base + 2 * lane;
    const int bmax0 = sort_bucket(b0);
    const int bmax1 = sort_bucket(b0 + 1);
    int x = max(bmax0, bmax1);
    #pragma unroll
    for (int d = 1; d < 32; d <<= 1) {
        int y = __shfl_up_sync(0xffffffffu, x, d);
        if (lane >= d) x = max(x, y);
    }
    int P = __shfl_up_sync(0xffffffffu, x, 1);
    if (lane == 0) P = -1;
    g_carry[b0]     = P;
    g_carry[b0 + 1] = max(P, bmax0);
}

// ---------------------------------------------------------------------------
// Fused output kernel: adj forward-fill + samples gather-concat, 256b stores.
// ---------------------------------------------------------------------------
__global__ void __launch_bounds__(256) fused_kernel(
    const float* __restrict__ emb,
    const float* __restrict__ sw,
    const int*   __restrict__ idx_in,
    const float* __restrict__ edge,
    float* __restrict__ out)
{
    if (blockIdx.x < FILL_BLKS) {
        // ---- adj fill: thread owns 8 adjacent columns within one row tile --
        float* __restrict__ adj = out + SAMPLES_ELEMS;
        const int b  = blockIdx.x;
        const int tt = b >> 2;                       // tile index (0..63)
        const int r0 = tt * TILE_R;
        const int c0 = (b & 3) * 2048 + threadIdx.x * 8;

        int   pos[8], m[8], nxt[8], bas[8];
        float val[8];
        int nxt_min = 0x7fffffff;
        #pragma unroll
        for (int u = 0; u < 8; u++) {
            const int bid = (c0 + u) * N_TILES + tt;
            int mm = __ldg(&g_cnt[bid]); if (mm > CAP) mm = CAP;
            m[u] = mm; bas[u] = bid * CAP; pos[u] = 0;
            nxt[u] = (mm > 0) ? __ldg(&g_bkt[bid * CAP]) : 0x7fffffff;
            nxt_min = min(nxt_min, nxt[u]);
            const int cts = __ldg(&g_carry[bid]);
            val[u] = (cts >= 0) ? __ldg(&edge[cts]) : 0.0f;
        }

        long long off = (long long)r0 * N_NODES + c0;
        for (int i = 0; i < TILE_R; i++) {
            const int lim = (r0 + i + 1) * K_NB;     // events with row <= r0+i
            if (nxt_min < lim) {                     // rare slow path
                nxt_min = 0x7fffffff;
                #pragma unroll
                for (int u = 0; u < 8; u++) {
                    while (nxt[u] < lim) {
                        val[u] = __ldg(&edge[nxt[u]]);
                        pos[u]++;
                        nxt[u] = (pos[u] < m[u]) ? __ldg(&g_bkt[bas[u] + pos[u]])
                                                 : 0x7fffffff;
                    }
                    nxt_min = min(nxt_min, nxt[u]);
                }
            }
            stg256(adj + off, val);
            off += N_NODES;
        }
    } else {
        // ---- samples: one node per block; 8-row groups; 256b stores --------
        const int i = blockIdx.x - FILL_BLKS;
        const int t = threadIdx.x;

        __shared__ float node_row[F_DIM];
        __shared__ int   nidx[K_NB];
        if (t < F_DIM) node_row[t] = __ldg(&emb[i * F_DIM + t]);
        if (t < K_NB)  nidx[t] = (t < K_NB - 1) ? __ldg(&idx_in[i * (K_NB - 1) + t]) : i;
        __syncthreads();

        // 8-row group = 2056 floats = 257 float8s, each group base 32B-aligned.
        float* __restrict__ obase = out + (long long)i * K_NB * ROW_LEN;

        const int nq = (t == 0) ? 2 : 1;             // thread 0 also covers q=256
        for (int s = 0; s < nq; s++) {
            const int q = (s == 0) ? t : 256;
            // Fixed per-lane classification (identical across all 8 groups).
            int   col_l[8];
            bool  useA[8];
            float nodev[8];
            const int rA = (8 * q)     / ROW_LEN;    // row of lane 0
            const int rB = (8 * q + 7) / ROW_LEN;    // row of lane 7 (<= rA+1)
            bool allnode = true;
            #pragma unroll
            for (int l = 0; l < 8; l++) {
                const int ff = 8 * q + l;
                const int rw = ff / ROW_LEN;
                col_l[l] = ff - rw * ROW_LEN;
                useA[l]  = (rw == rA);
                nodev[l] = (col_l[l] < F_DIM) ? node_row[col_l[l]] : 0.0f;
                allnode &= (col_l[l] < F_DIM);
            }

            if (allnode) {                           // loop-invariant value
                #pragma unroll
                for (int g = 0; g < 8; g++)
                    stg256(obase + (long long)(g * 257 + q) * 8, nodev);
            } else {
                #pragma unroll 2
                for (int g = 0; g < 8; g++) {
                    const int cA = nidx[8 * g + rA];
                    const int cB = (rB != rA) ? nidx[8 * g + rB] : cA;
                    float v[8];
                    #pragma unroll
                    for (int l = 0; l < 8; l++) {
                        const int c   = useA[l] ? cA : cB;
                        const int col = col_l[l];
                        float x;
                        if (col < F_DIM)          x = nodev[l];
                        else if (col < 2 * F_DIM) x = __ldg(&emb[c * F_DIM + (col - F_DIM)]);
                        else                      x = __ldg(&sw[c]);
                        v[l] = x;
                    }
                    stg256(obase + (long long)(g * 257 + q) * 8, v);
                }
            }
        }
    }
}

// ---------------------------------------------------------------------------
extern "C" void kernel_launch(void* const* d_in, const int* in_sizes, int n_in,
                              void* d_out, int out_size) {
    const float* emb      = (const float*)d_in[0];   // [8192, 128]
    const float* sw       = (const float*)d_in[1];   // [8192]
    const int*   idx_in   = (const int*)  d_in[2];   // [8192, 63]
    const float* edge_out = (const float*)d_in[3];   // [8192, 64]
    float* out = (float*)d_out;

    zero_kernel     <<<NB / 4096, 1024>>>();         // int4-vectorized
    scatter_kernel  <<<TOTAL_E / 256, 256>>>(idx_in);
    sortcarry_kernel<<<N_NODES / 8, 256>>>();        // warp per column
    fused_kernel    <<<FILL_BLKS + N_NODES, 256>>>(emb, sw, idx_in, edge_out, out);
}

// round 6
// speedup vs baseline: 1.1850x; 1.1850x over previous
#include <cuda_runtime.h>
#include <cuda_bf16.h>

// Problem constants (fixed by the reference)
#define N_NODES 8192
#define K_NB    64
#define F_DIM   128
#define ROW_LEN 257                         // 2F+1
#define TOTAL_E (N_NODES * K_NB)            // 524288 write events
#define SAMPLES_ELEMS ((long long)TOTAL_E * ROW_LEN)
#define TILE_R   128                        // rows per fill tile
#define N_TILES  (N_NODES / TILE_R)         // 64
#define CAP      16                         // per-(col,tile) bucket cap (Poisson(1))
#define NB       (N_NODES * N_TILES)        // 524288 micro-buckets
#define FILL_BLKS 512                       // 64 row-tiles * 8 col-blocks (4 cols/thread)

// Scratch (allocation-free __device__ globals)
__device__ int g_cnt[NB];                   // 2 MB  events per (col,tile)
__device__ int g_bkt[NB * CAP];             // 32 MB timestamps
__device__ int g_carry[NB];                 // 2 MB  max ts in tiles < t (-1 if none)

// ---------------------------------------------------------------------------
__global__ void zero_kernel() {
    ((int4*)g_cnt)[blockIdx.x * blockDim.x + threadIdx.x] = make_int4(0, 0, 0, 0);
}

// Scatter each event ts = r*K+j into micro-bucket (col, r/TILE_R).
__global__ void scatter_kernel(const int* __restrict__ idx_in) {
    const int e = blockIdx.x * blockDim.x + threadIdx.x;
    const int r = e >> 6;
    const int j = e & (K_NB - 1);
    const int c = (j < K_NB - 1) ? __ldg(&idx_in[r * (K_NB - 1) + j]) : r;
    const int bid = c * N_TILES + (r >> 7);
    const int p = atomicAdd(&g_cnt[bid], 1);
    if (p < CAP) g_bkt[bid * CAP + p] = e;
}

// Warp per column: sort each micro-bucket (mean 1 event), then exclusive
// prefix-max of bucket maxima over the 64 tiles -> carry-in timestamps.
__device__ __forceinline__ int sort_bucket(int b) {
    int m = g_cnt[b]; if (m > CAP) m = CAP;
    int* __restrict__ a = &g_bkt[b * CAP];
    for (int i = 1; i < m; i++) {
        int v = a[i], j = i - 1;
        while (j >= 0 && a[j] > v) { a[j + 1] = a[j]; j--; }
        a[j + 1] = v;
    }
    return (m > 0) ? a[m - 1] : -1;          // bucket max ts (sorted => last)
}

__global__ void sortcarry_kernel() {
    const int c    = blockIdx.x * 8 + (threadIdx.x >> 5);
    const int lane = threadIdx.x & 31;
    const int b0   = c * N_TILES + 2 * lane;
    const int bmax0 = sort_bucket(b0);
    const int bmax1 = sort_bucket(b0 + 1);
    int x = max(bmax0, bmax1);
    #pragma unroll
    for (int d = 1; d < 32; d <<= 1) {
        int y = __shfl_up_sync(0xffffffffu, x, d);
        if (lane >= d) x = max(x, y);
    }
    int P = __shfl_up_sync(0xffffffffu, x, 1);
    if (lane == 0) P = -1;
    g_carry[b0]     = P;
    g_carry[b0 + 1] = max(P, bmax0);
}

// ---------------------------------------------------------------------------
// Fused output kernel: adj forward-fill + samples gather-concat, float4 stores.
// ---------------------------------------------------------------------------
__global__ void __launch_bounds__(256) fused_kernel(
    const float* __restrict__ emb,
    const float* __restrict__ sw,
    const int*   __restrict__ idx_in,
    const float* __restrict__ edge,
    float* __restrict__ out)
{
    if (blockIdx.x < FILL_BLKS) {
        // ---- adj fill: thread owns 4 adjacent columns within one row tile --
        float* __restrict__ adj = out + SAMPLES_ELEMS;
        const int b  = blockIdx.x;
        const int tt = b >> 3;                       // tile index (0..63)
        const int r0 = tt * TILE_R;
        const int c0 = (b & 7) * 1024 + threadIdx.x * 4;

        int   pos[4], m[4], nxt[4], bas[4];
        float val[4];
        int nxt_min = 0x7fffffff;
        #pragma unroll
        for (int u = 0; u < 4; u++) {
            const int bid = (c0 + u) * N_TILES + tt;
            int mm = __ldg(&g_cnt[bid]); if (mm > CAP) mm = CAP;
            m[u] = mm; bas[u] = bid * CAP; pos[u] = 0;
            nxt[u] = (mm > 0) ? __ldg(&g_bkt[bid * CAP]) : 0x7fffffff;
            nxt_min = min(nxt_min, nxt[u]);
            const int cts = __ldg(&g_carry[bid]);
            val[u] = (cts >= 0) ? __ldg(&edge[cts]) : 0.0f;
        }

        long long off = (long long)r0 * N_NODES + c0;
        for (int i = 0; i < TILE_R; i++) {
            const int lim = (r0 + i + 1) * K_NB;     // events with row <= r0+i
            if (nxt_min < lim) {                     // rare slow path
                nxt_min = 0x7fffffff;
                #pragma unroll
                for (int u = 0; u < 4; u++) {
                    while (nxt[u] < lim) {
                        val[u] = __ldg(&edge[nxt[u]]);
                        pos[u]++;
                        nxt[u] = (pos[u] < m[u]) ? __ldg(&g_bkt[bas[u] + pos[u]])
                                                 : 0x7fffffff;
                    }
                    nxt_min = min(nxt_min, nxt[u]);
                }
            }
            *(float4*)(adj + off) = make_float4(val[0], val[1], val[2], val[3]);
            off += N_NODES;
        }
    } else {
        // ---- samples: one node per block; 4-row groups; float4 stores ------
        const int i = blockIdx.x - FILL_BLKS;
        const int t = threadIdx.x;

        __shared__ float node_row[F_DIM];
        __shared__ int   nidx[K_NB];
        if (t < F_DIM) node_row[t] = __ldg(&emb[i * F_DIM + t]);
        if (t < K_NB)  nidx[t] = (t < K_NB - 1) ? __ldg(&idx_in[i * (K_NB - 1) + t]) : i;
        __syncthreads();

        // 4-row group = 1028 floats = 257 float4s, each group base 16B-aligned.
        float4* __restrict__ outv = (float4*)(out + (long long)i * K_NB * ROW_LEN);

        const int nq = (t == 0) ? 2 : 1;             // thread 0 also covers q=256
        for (int s = 0; s < nq; s++) {
            const int q = (s == 0) ? t : 256;
            // Fixed per-lane classification (identical across all 16 groups).
            // A float4 spans at most 2 sample rows: rA (lane 0) and rB (lane 3).
            const int rA = (4 * q)     / ROW_LEN;
            const int rB = (4 * q + 3) / ROW_LEN;
            int   col_l[4];
            bool  useA[4];
            float nodev[4];
            bool allnode = true;
            #pragma unroll
            for (int l = 0; l < 4; l++) {
                const int ff = 4 * q + l;
                const int rw = ff / ROW_LEN;
                col_l[l] = ff - rw * ROW_LEN;
                useA[l]  = (rw == rA);
                nodev[l] = (col_l[l] < F_DIM) ? node_row[col_l[l]] : 0.0f;
                allnode &= (col_l[l] < F_DIM);
            }

            if (allnode) {                           // loop-invariant value
                const float4 nv = make_float4(nodev[0], nodev[1], nodev[2], nodev[3]);
                #pragma unroll
                for (int g = 0; g < 16; g++)
                    outv[g * 257 + q] = nv;
            } else {
                #pragma unroll 4
                for (int g = 0; g < 16; g++) {
                    const int cA = nidx[4 * g + rA];
                    const int cB = (rB != rA) ? nidx[4 * g + rB] : cA;
                    float4 v;
                    #pragma unroll
                    for (int l = 0; l < 4; l++) {
                        const int c   = useA[l] ? cA : cB;
                        const int col = col_l[l];
                        float x;
                        if (col < F_DIM)          x = nodev[l];
                        else if (col < 2 * F_DIM) x = __ldg(&emb[c * F_DIM + (col - F_DIM)]);
                        else                      x = __ldg(&sw[c]);
                        ((float*)&v)[l] = x;
                    }
                    outv[g * 257 + q] = v;
                }
            }
        }
    }
}

// ---------------------------------------------------------------------------
extern "C" void kernel_launch(void* const* d_in, const int* in_sizes, int n_in,
                              void* d_out, int out_size) {
    const float* emb      = (const float*)d_in[0];   // [8192, 128]
    const float* sw       = (const float*)d_in[1];   // [8192]
    const int*   idx_in   = (const int*)  d_in[2];   // [8192, 63]
    const float* edge_out = (const float*)d_in[3];   // [8192, 64]
    float* out = (float*)d_out;

    zero_kernel     <<<NB / 4096, 1024>>>();         // int4-vectorized
    scatter_kernel  <<<TOTAL_E / 256, 256>>>(idx_in);
    sortcarry_kernel<<<N_NODES / 8, 256>>>();        // warp per column
    fused_kernel    <<<FILL_BLKS + N_NODES, 256>>>(emb, sw, idx_in, edge_out, out);
}

// round 7
// speedup vs baseline: 1.1999x; 1.0126x over previous
#include <cuda_runtime.h>
#include <cuda_bf16.h>

// Problem constants (fixed by the reference)
#define N_NODES 8192
#define K_NB    64
#define F_DIM   128
#define ROW_LEN 257                         // 2F+1
#define TOTAL_E (N_NODES * K_NB)            // 524288 write events
#define SAMPLES_ELEMS ((long long)TOTAL_E * ROW_LEN)
#define TILE_R   128                        // rows per fill tile
#define N_TILES  (N_NODES / TILE_R)         // 64
#define CAP      16                         // per-(col,tile) bucket cap (Poisson(1))
#define NB       (N_NODES * N_TILES)        // 524288 micro-buckets
#define FILL_BLKS 512                       // 64 row-tiles * 8 col-blocks (4 cols/thread)

// Scratch (allocation-free __device__ globals)
__device__ int g_cnt[NB];                   // 2 MB  events per (col,tile)
__device__ int g_bkt[NB * CAP];             // 32 MB timestamps
__device__ int g_carry[NB];                 // 2 MB  max ts in tiles < t (-1 if none)

// ---------------------------------------------------------------------------
__global__ void zero_kernel() {
    ((int4*)g_cnt)[blockIdx.x * blockDim.x + threadIdx.x] = make_int4(0, 0, 0, 0);
}

// Scatter each event ts = r*K+j into micro-bucket (col, r/TILE_R).
__global__ void scatter_kernel(const int* __restrict__ idx_in) {
    const int e = blockIdx.x * blockDim.x + threadIdx.x;
    const int r = e >> 6;
    const int j = e & (K_NB - 1);
    const int c = (j < K_NB - 1) ? __ldg(&idx_in[r * (K_NB - 1) + j]) : r;
    const int bid = c * N_TILES + (r >> 7);
    const int p = atomicAdd(&g_cnt[bid], 1);
    if (p < CAP) g_bkt[bid * CAP + p] = e;
}

// Warp per column: sort each micro-bucket (mean 1 event), then exclusive
// prefix-max of bucket maxima over the 64 tiles -> carry-in timestamps.
__device__ __forceinline__ int sort_bucket(int b) {
    int m = g_cnt[b]; if (m > CAP) m = CAP;
    int* __restrict__ a = &g_bkt[b * CAP];
    for (int i = 1; i < m; i++) {
        int v = a[i], j = i - 1;
        while (j >= 0 && a[j] > v) { a[j + 1] = a[j]; j--; }
        a[j + 1] = v;
    }
    return (m > 0) ? a[m - 1] : -1;          // bucket max ts (sorted => last)
}

__global__ void sortcarry_kernel() {
    const int c    = blockIdx.x * 8 + (threadIdx.x >> 5);
    const int lane = threadIdx.x & 31;
    const int b0   = c * N_TILES + 2 * lane;
    const int bmax0 = sort_bucket(b0);
    const int bmax1 = sort_bucket(b0 + 1);
    int x = max(bmax0, bmax1);
    #pragma unroll
    for (int d = 1; d < 32; d <<= 1) {
        int y = __shfl_up_sync(0xffffffffu, x, d);
        if (lane >= d) x = max(x, y);
    }
    int P = __shfl_up_sync(0xffffffffu, x, 1);
    if (lane == 0) P = -1;
    g_carry[b0]     = P;
    g_carry[b0 + 1] = max(P, bmax0);
}

// ---------------------------------------------------------------------------
// Fused output kernel: adj forward-fill + samples gather-concat, float4 stores.
// (Round-3 body: minimal per-lane state, 4-way select, register-cached nxt.)
// ---------------------------------------------------------------------------
__global__ void __launch_bounds__(256) fused_kernel(
    const float* __restrict__ emb,
    const float* __restrict__ sw,
    const int*   __restrict__ idx_in,
    const float* __restrict__ edge,
    float* __restrict__ out)
{
    if (blockIdx.x < FILL_BLKS) {
        // ---- adj fill: thread owns 4 adjacent columns within one row tile --
        float* __restrict__ adj = out + SAMPLES_ELEMS;
        const int b  = blockIdx.x;
        const int tt = b >> 3;                       // tile index (0..63)
        const int r0 = tt * TILE_R;
        const int c0 = (b & 7) * 1024 + threadIdx.x * 4;

        int   pos[4], m[4], nxt[4], bas[4];
        float val[4];
        int nxt_min = 0x7fffffff;
        #pragma unroll
        for (int u = 0; u < 4; u++) {
            const int bid = (c0 + u) * N_TILES + tt;
            int mm = __ldg(&g_cnt[bid]); if (mm > CAP) mm = CAP;
            m[u] = mm; bas[u] = bid * CAP; pos[u] = 0;
            nxt[u] = (mm > 0) ? __ldg(&g_bkt[bid * CAP]) : 0x7fffffff;
            nxt_min = min(nxt_min, nxt[u]);
            const int cts = __ldg(&g_carry[bid]);
            val[u] = (cts >= 0) ? __ldg(&edge[cts]) : 0.0f;
        }

        long long off = (long long)r0 * N_NODES + c0;
        for (int i = 0; i < TILE_R; i++) {
            const int lim = (r0 + i + 1) * K_NB;     // events with row <= r0+i
            if (nxt_min < lim) {                     // rare slow path
                nxt_min = 0x7fffffff;
                #pragma unroll
                for (int u = 0; u < 4; u++) {
                    while (nxt[u] < lim) {
                        val[u] = __ldg(&edge[nxt[u]]);
                        pos[u]++;
                        nxt[u] = (pos[u] < m[u]) ? __ldg(&g_bkt[bas[u] + pos[u]])
                                                 : 0x7fffffff;
                    }
                    nxt_min = min(nxt_min, nxt[u]);
                }
            }
            *(float4*)(adj + off) = make_float4(val[0], val[1], val[2], val[3]);
            off += N_NODES;
        }
    } else {
        // ---- samples: one node per block; per-lane mapping hoisted ---------
        const int i = blockIdx.x - FILL_BLKS;
        const int t = threadIdx.x;

        __shared__ float node_row[F_DIM];
        __shared__ int4  nidx4[16];                  // 64 neighbor indices
        if (t < F_DIM) node_row[t] = __ldg(&emb[i * F_DIM + t]);
        if (t < K_NB)  ((int*)nidx4)[t] =
            (t < K_NB - 1) ? __ldg(&idx_in[i * (K_NB - 1) + t]) : i;
        __syncthreads();

        float4* __restrict__ outv = (float4*)(out + (long long)i * K_NB * ROW_LEN);

        // Thread t covers q = t; thread 0 also covers q = 256.
        const int nq = (t == 0) ? 2 : 1;
        for (int s = 0; s < nq; s++) {
            const int q = (s == 0) ? t : 256;
            // Fixed per-lane classification (identical across all 16 groups).
            int   row_l[4], col_l[4];
            float nodev[4];
            #pragma unroll
            for (int l = 0; l < 4; l++) {
                const int ff = 4 * q + l;
                const int rw = (ff >= 257) + (ff >= 514) + (ff >= 771);
                row_l[l] = rw;
                col_l[l] = ff - rw * ROW_LEN;
                nodev[l] = (col_l[l] < F_DIM) ? node_row[col_l[l]] : 0.0f;
            }
            #pragma unroll 4
            for (int g = 0; g < 16; g++) {
                const int4 nb = nidx4[g];            // neighbor ids for rows 4g..4g+3
                float4 v;
                #pragma unroll
                for (int l = 0; l < 4; l++) {
                    const int rw = row_l[l];
                    const int c  = (rw == 0) ? nb.x : (rw == 1) ? nb.y
                                 : (rw == 2) ? nb.z : nb.w;
                    const int col = col_l[l];
                    float x;
                    if (col < F_DIM)          x = nodev[l];
                    else if (col < 2 * F_DIM) x = __ldg(&emb[c * F_DIM + (col - F_DIM)]);
                    else                      x = __ldg(&sw[c]);
                    ((float*)&v)[l] = x;
                }
                outv[g * 257 + q] = v;
            }
        }
    }
}

// ---------------------------------------------------------------------------
extern "C" void kernel_launch(void* const* d_in, const int* in_sizes, int n_in,
                              void* d_out, int out_size) {
    const float* emb      = (const float*)d_in[0];   // [8192, 128]
    const float* sw       = (const float*)d_in[1];   // [8192]
    const int*   idx_in   = (const int*)  d_in[2];   // [8192, 63]
    const float* edge_out = (const float*)d_in[3];   // [8192, 64]
    float* out = (float*)d_out;

    zero_kernel     <<<NB / 4096, 1024>>>();         // int4-vectorized
    scatter_kernel  <<<TOTAL_E / 256, 256>>>(idx_in);
    sortcarry_kernel<<<N_NODES / 8, 256>>>();        // warp per column
    fused_kernel    <<<FILL_BLKS + N_NODES, 256>>>(emb, sw, idx_in, edge_out, out);
}

// round 8
// speedup vs baseline: 1.2824x; 1.0687x over previous
#include <cuda_runtime.h>
#include <cuda_bf16.h>

// Problem constants (fixed by the reference)
#define N_NODES 8192
#define K_NB    64
#define F_DIM   128
#define ROW_LEN 257                         // 2F+1
#define TOTAL_E (N_NODES * K_NB)            // 524288 write events
#define SAMPLES_ELEMS ((long long)TOTAL_E * ROW_LEN)
#define TILE_R   128                        // rows per fill tile
#define N_TILES  (N_NODES / TILE_R)         // 64
#define CAP      16                         // per-(col,tile) bucket cap (Poisson(1))
#define NB       (N_NODES * N_TILES)        // 524288 micro-buckets
#define FILL_BLKS 512                       // 64 row-tiles * 8 col-blocks (4 cols/thread)

// Scratch (allocation-free __device__ globals)
__device__ int g_cnt[NB];                   // 2 MB  events per (col,tile)
__device__ int g_bkt[NB * CAP];             // 32 MB timestamps
__device__ int g_carry[NB];                 // 2 MB  max ts in tiles < t (-1 if none)

// ---------------------------------------------------------------------------
__global__ void zero_kernel() {
    ((int4*)g_cnt)[blockIdx.x * blockDim.x + threadIdx.x] = make_int4(0, 0, 0, 0);
}

// Scatter each event ts = r*K+j into micro-bucket (col, r/TILE_R).
__global__ void scatter_kernel(const int* __restrict__ idx_in) {
    const int e = blockIdx.x * blockDim.x + threadIdx.x;
    const int r = e >> 6;
    const int j = e & (K_NB - 1);
    const int c = (j < K_NB - 1) ? __ldg(&idx_in[r * (K_NB - 1) + j]) : r;
    const int bid = c * N_TILES + (r >> 7);
    const int p = atomicAdd(&g_cnt[bid], 1);
    if (p < CAP) g_bkt[bid * CAP + p] = e;
}

// Warp per column: sort each micro-bucket (mean 1 event), then exclusive
// prefix-max of bucket maxima over the 64 tiles -> carry-in timestamps.
__device__ __forceinline__ int sort_bucket(int b) {
    int m = g_cnt[b]; if (m > CAP) m = CAP;
    int* __restrict__ a = &g_bkt[b * CAP];
    for (int i = 1; i < m; i++) {
        int v = a[i], j = i - 1;
        while (j >= 0 && a[j] > v) { a[j + 1] = a[j]; j--; }
        a[j + 1] = v;
    }
    return (m > 0) ? a[m - 1] : -1;          // bucket max ts (sorted => last)
}

__global__ void sortcarry_kernel() {
    const int c    = blockIdx.x * 8 + (threadIdx.x >> 5);
    const int lane = threadIdx.x & 31;
    const int b0   = c * N_TILES + 2 * lane;
    const int bmax0 = sort_bucket(b0);
    const int bmax1 = sort_bucket(b0 + 1);
    int x = max(bmax0, bmax1);
    #pragma unroll
    for (int d = 1; d < 32; d <<= 1) {
        int y = __shfl_up_sync(0xffffffffu, x, d);
        if (lane >= d) x = max(x, y);
    }
    int P = __shfl_up_sync(0xffffffffu, x, 1);
    if (lane == 0) P = -1;
    g_carry[b0]     = P;
    g_carry[b0 + 1] = max(P, bmax0);
}

// ---------------------------------------------------------------------------
// Fused output kernel: adj forward-fill + samples gather-concat, float4 stores.
// Exact Round-3 body (30 regs / 82% occ measured); launch bounds pin the
// 32-register / 8-blocks-per-SM point so the compiler cannot drift off it.
// ---------------------------------------------------------------------------
__global__ void __launch_bounds__(256, 8) fused_kernel(
    const float* __restrict__ emb,
    const float* __restrict__ sw,
    const int*   __restrict__ idx_in,
    const float* __restrict__ edge,
    float* __restrict__ out)
{
    if (blockIdx.x < FILL_BLKS) {
        // ---- adj fill: thread owns 4 adjacent columns within one row tile --
        float* __restrict__ adj = out + SAMPLES_ELEMS;
        const int b  = blockIdx.x;
        const int tt = b >> 3;                       // tile index (0..63)
        const int r0 = tt * TILE_R;
        const int c0 = (b & 7) * 1024 + threadIdx.x * 4;

        int   pos[4], m[4], nxt[4], bas[4];
        float val[4];
        #pragma unroll
        for (int u = 0; u < 4; u++) {
            const int bid = (c0 + u) * N_TILES + tt;
            int mm = __ldg(&g_cnt[bid]); if (mm > CAP) mm = CAP;
            m[u] = mm; bas[u] = bid * CAP; pos[u] = 0;
            nxt[u] = (mm > 0) ? __ldg(&g_bkt[bid * CAP]) : 0x7fffffff;
            const int cts = __ldg(&g_carry[bid]);
            val[u] = (cts >= 0) ? __ldg(&edge[cts]) : 0.0f;
        }

        long long off = (long long)r0 * N_NODES + c0;
        for (int i = 0; i < TILE_R; i++) {
            const int lim = (r0 + i + 1) * K_NB;     // events with row <= r0+i
            float4 v;
            #pragma unroll
            for (int u = 0; u < 4; u++) {
                while (nxt[u] < lim) {               // register compare; rare advance
                    val[u] = __ldg(&edge[nxt[u]]);
                    pos[u]++;
                    nxt[u] = (pos[u] < m[u]) ? __ldg(&g_bkt[bas[u] + pos[u]])
                                             : 0x7fffffff;
                }
                ((float*)&v)[u] = val[u];
            }
            *(float4*)(adj + off) = v;
            off += N_NODES;
        }
    } else {
        // ---- samples: one node per block; per-lane mapping hoisted ---------
        const int i = blockIdx.x - FILL_BLKS;
        const int t = threadIdx.x;

        __shared__ float node_row[F_DIM];
        __shared__ int4  nidx4[16];                  // 64 neighbor indices
        if (t < F_DIM) node_row[t] = __ldg(&emb[i * F_DIM + t]);
        if (t < K_NB)  ((int*)nidx4)[t] =
            (t < K_NB - 1) ? __ldg(&idx_in[i * (K_NB - 1) + t]) : i;
        __syncthreads();

        float4* __restrict__ outv = (float4*)(out + (long long)i * K_NB * ROW_LEN);

        // Thread t covers q = t; thread 0 also covers q = 256.
        const int nq = (t == 0) ? 2 : 1;
        for (int s = 0; s < nq; s++) {
            const int q = (s == 0) ? t : 256;
            // Fixed per-lane classification (identical across all 16 groups).
            int   row_l[4], col_l[4];
            float nodev[4];
            #pragma unroll
            for (int l = 0; l < 4; l++) {
                const int ff = 4 * q + l;
                const int rw = (ff >= 257) + (ff >= 514) + (ff >= 771);
                row_l[l] = rw;
                col_l[l] = ff - rw * ROW_LEN;
                nodev[l] = (col_l[l] < F_DIM) ? node_row[col_l[l]] : 0.0f;
            }
            #pragma unroll 4
            for (int g = 0; g < 16; g++) {
                const int4 nb = nidx4[g];            // neighbor ids for rows 4g..4g+3
                float4 v;
                #pragma unroll
                for (int l = 0; l < 4; l++) {
                    const int rw = row_l[l];
                    const int c  = (rw == 0) ? nb.x : (rw == 1) ? nb.y
                                 : (rw == 2) ? nb.z : nb.w;
                    const int col = col_l[l];
                    float x;
                    if (col < F_DIM)          x = nodev[l];
                    else if (col < 2 * F_DIM) x = __ldg(&emb[c * F_DIM + (col - F_DIM)]);
                    else                      x = __ldg(&sw[c]);
                    ((float*)&v)[l] = x;
                }
                outv[g * 257 + q] = v;
            }
        }
    }
}

// ---------------------------------------------------------------------------
extern "C" void kernel_launch(void* const* d_in, const int* in_sizes, int n_in,
                              void* d_out, int out_size) {
    const float* emb      = (const float*)d_in[0];   // [8192, 128]
    const float* sw       = (const float*)d_in[1];   // [8192]
    const int*   idx_in   = (const int*)  d_in[2];   // [8192, 63]
    const float* edge_out = (const float*)d_in[3];   // [8192, 64]
    float* out = (float*)d_out;

    zero_kernel     <<<NB / 4096, 1024>>>();         // int4-vectorized
    scatter_kernel  <<<TOTAL_E / 256, 256>>>(idx_in);
    sortcarry_kernel<<<N_NODES / 8, 256>>>();        // warp per column
    fused_kernel    <<<FILL_BLKS + N_NODES, 256>>>(emb, sw, idx_in, edge_out, out);
}

// round 10
// speedup vs baseline: 1.4520x; 1.1323x over previous
#include <cuda_runtime.h>
#include <cuda_bf16.h>

// Problem constants (fixed by the reference)
#define N_NODES 8192
#define K_NB    64
#define F_DIM   128
#define ROW_LEN 257                         // 2F+1
#define TOTAL_E (N_NODES * K_NB)            // 524288 write events
#define SAMPLES_ELEMS ((long long)TOTAL_E * ROW_LEN)
#define TILE_R   128                        // rows per fill tile
#define N_TILES  (N_NODES / TILE_R)         // 64
#define CAP      16                         // per-(col,tile) bucket cap (Poisson(1))
#define NB       (N_NODES * N_TILES)        // 524288 micro-buckets
#define FILL_BLKS 512                       // 64 row-tiles * 8 col-blocks (4 cols/thread)

// Scratch (allocation-free __device__ globals; zero-initialized at load).
// Invariant: g_cnt is all-zero on entry to scatter — restored each run by
// fill_kernel (the unique final reader of each bucket) resetting it.
__device__ int g_cnt[NB];                   // 2 MB  events per (col,tile)
__device__ int g_bkt[NB * CAP];             // 32 MB timestamps
__device__ int g_carry[NB];                 // 2 MB  max ts in tiles < t (-1 if none)

// ---------------------------------------------------------------------------
// Scatter each event ts = r*K+j into micro-bucket (col, r/TILE_R).
__global__ void scatter_kernel(const int* __restrict__ idx_in) {
    const int e = blockIdx.x * blockDim.x + threadIdx.x;
    const int r = e >> 6;
    const int j = e & (K_NB - 1);
    const int c = (j < K_NB - 1) ? __ldg(&idx_in[r * (K_NB - 1) + j]) : r;
    const int bid = c * N_TILES + (r >> 7);
    const int p = atomicAdd(&g_cnt[bid], 1);
    if (p < CAP) g_bkt[bid * CAP + p] = e;
}

// Warp per column: sort each micro-bucket (mean 1 event), then exclusive
// prefix-max of bucket maxima over the 64 tiles -> carry-in timestamps.
__device__ __forceinline__ int sort_bucket(int b) {
    int m = g_cnt[b]; if (m > CAP) m = CAP;
    int* __restrict__ a = &g_bkt[b * CAP];
    for (int i = 1; i < m; i++) {
        int v = a[i], j = i - 1;
        while (j >= 0 && a[j] > v) { a[j + 1] = a[j]; j--; }
        a[j + 1] = v;
    }
    return (m > 0) ? a[m - 1] : -1;          // bucket max ts (sorted => last)
}

__global__ void sortcarry_kernel() {
    const int c    = blockIdx.x * 8 + (threadIdx.x >> 5);
    const int lane = threadIdx.x & 31;
    const int b0   = c * N_TILES + 2 * lane;
    const int bmax0 = sort_bucket(b0);
    const int bmax1 = sort_bucket(b0 + 1);
    int x = max(bmax0, bmax1);
    #pragma unroll
    for (int d = 1; d < 32; d <<= 1) {
        int y = __shfl_up_sync(0xffffffffu, x, d);
        if (lane >= d) x = max(x, y);
    }
    int P = __shfl_up_sync(0xffffffffu, x, 1);
    if (lane == 0) P = -1;
    g_carry[b0]     = P;
    g_carry[b0 + 1] = max(P, bmax0);
}

// ---------------------------------------------------------------------------
// adj forward-fill: thread owns 4 adjacent columns within one row tile.
// (R8 fill body; also resets g_cnt for the next graph replay.)
// ---------------------------------------------------------------------------
__global__ void __launch_bounds__(256, 8) fill_kernel(
    const float* __restrict__ edge, float* __restrict__ out)
{
    float* __restrict__ adj = out + SAMPLES_ELEMS;
    const int b  = blockIdx.x;
    const int tt = b >> 3;                       // tile index (0..63)
    const int r0 = tt * TILE_R;
    const int c0 = (b & 7) * 1024 + threadIdx.x * 4;

    int   pos[4], m[4], nxt[4], bas[4];
    float val[4];
    #pragma unroll
    for (int u = 0; u < 4; u++) {
        const int bid = (c0 + u) * N_TILES + tt;
        int mm = g_cnt[bid]; if (mm > CAP) mm = CAP;
        g_cnt[bid] = 0;                          // consumer reset (sole owner)
        m[u] = mm; bas[u] = bid * CAP; pos[u] = 0;
        nxt[u] = (mm > 0) ? __ldg(&g_bkt[bid * CAP]) : 0x7fffffff;
        const int cts = __ldg(&g_carry[bid]);
        val[u] = (cts >= 0) ? __ldg(&edge[cts]) : 0.0f;
    }

    long long off = (long long)r0 * N_NODES + c0;
    for (int i = 0; i < TILE_R; i++) {
        const int lim = (r0 + i + 1) * K_NB;     // events with row <= r0+i
        float4 v;
        #pragma unroll
        for (int u = 0; u < 4; u++) {
            while (nxt[u] < lim) {               // register compare; rare advance
                val[u] = __ldg(&edge[nxt[u]]);
                pos[u]++;
                nxt[u] = (pos[u] < m[u]) ? __ldg(&g_bkt[bas[u] + pos[u]])
                                         : 0x7fffffff;
            }
            ((float*)&v)[u] = val[u];
        }
        __stcs((float4*)(adj + off), v);         // streaming: write-once data
        off += N_NODES;
    }
}

// ---------------------------------------------------------------------------
// samples gather-concat: one node per block, float4 stores. (R8 body.)
// ---------------------------------------------------------------------------
__global__ void __launch_bounds__(256, 8) samples_kernel(
    const float* __restrict__ emb,
    const float* __restrict__ sw,
    const int*   __restrict__ idx_in,
    float* __restrict__ out)
{
    const int i = blockIdx.x;
    const int t = threadIdx.x;

    __shared__ float node_row[F_DIM];
    __shared__ int4  nidx4[16];                  // 64 neighbor indices
    if (t < F_DIM) node_row[t] = __ldg(&emb[i * F_DIM + t]);
    if (t < K_NB)  ((int*)nidx4)[t] =
        (t < K_NB - 1) ? __ldg(&idx_in[i * (K_NB - 1) + t]) : i;
    __syncthreads();

    float4* __restrict__ outv = (float4*)(out + (long long)i * K_NB * ROW_LEN);

    // Thread t covers q = t; thread 0 also covers q = 256.
    const int nq = (t == 0) ? 2 : 1;
    for (int s = 0; s < nq; s++) {
        const int q = (s == 0) ? t : 256;
        // Fixed per-lane classification (identical across all 16 groups).
        int   row_l[4], col_l[4];
        float nodev[4];
        #pragma unroll
        for (int l = 0; l < 4; l++) {
            const int ff = 4 * q + l;
            const int rw = (ff >= 257) + (ff >= 514) + (ff >= 771);
            row_l[l] = rw;
            col_l[l] = ff - rw * ROW_LEN;
            nodev[l] = (col_l[l] < F_DIM) ? node_row[col_l[l]] : 0.0f;
        }
        #pragma unroll 4
        for (int g = 0; g < 16; g++) {
            const int4 nb = nidx4[g];            // neighbor ids for rows 4g..4g+3
            float4 v;
            #pragma unroll
            for (int l = 0; l < 4; l++) {
                const int rw = row_l[l];
                const int c  = (rw == 0) ? nb.x : (rw == 1) ? nb.y
                             : (rw == 2) ? nb.z : nb.w;
                const int col = col_l[l];
                float x;
                if (col < F_DIM)          x = nodev[l];
                else if (col < 2 * F_DIM) x = __ldg(&emb[c * F_DIM + (col - F_DIM)]);
                else                      x = __ldg(&sw[c]);
                ((float*)&v)[l] = x;
            }
            __stcs(&outv[g * 257 + q], v);       // streaming: write-once data
        }
    }
}

// ---------------------------------------------------------------------------
// Fork/join: samples (no deps) runs on the launch stream while the adj
// pipeline (scatter -> sortcarry -> fill) runs on a side stream. Stream and
// events are created lazily on the FIRST call — the harness's correctness
// run, which happens before graph capture — so no resource creation occurs
// during capture; during capture the event record/wait pattern forks and
// rejoins the capture graph (supported fork/join capture).
// ---------------------------------------------------------------------------
extern "C" void kernel_launch(void* const* d_in, const int* in_sizes, int n_in,
                              void* d_out, int out_size) {
    const float* emb      = (const float*)d_in[0];   // [8192, 128]
    const float* sw       = (const float*)d_in[1];   // [8192]
    const int*   idx_in   = (const int*)  d_in[2];   // [8192, 63]
    const float* edge_out = (const float*)d_in[3];   // [8192, 64]
    float* out = (float*)d_out;

    static cudaStream_t side = nullptr;
    static cudaEvent_t  ev_fork = nullptr, ev_join = nullptr;
    if (side == nullptr) {
        cudaStreamCreateWithFlags(&side, cudaStreamNonBlocking);
        cudaEventCreateWithFlags(&ev_fork, cudaEventDisableTiming);
        cudaEventCreateWithFlags(&ev_join, cudaEventDisableTiming);
    }

    // fork: side stream branches off the launch stream
    cudaEventRecord(ev_fork, 0);
    cudaStreamWaitEvent(side, ev_fork, 0);

    // adj pipeline on side stream (268 MB of the output)
    scatter_kernel  <<<TOTAL_E / 256, 256, 0, side>>>(idx_in);
    sortcarry_kernel<<<N_NODES / 8, 256, 0, side>>>();
    fill_kernel     <<<FILL_BLKS, 256, 0, side>>>(edge_out, out);
    cudaEventRecord(ev_join, side);

    // samples on the launch stream, concurrent with the side pipeline (539 MB)
    samples_kernel<<<N_NODES, 256>>>(emb, sw, idx_in, out);

    // join: launch stream waits for the side pipeline
    cudaStreamWaitEvent(0, ev_join, 0);
}

// round 12
// speedup vs baseline: 1.5952x; 1.0986x over previous
#include <cuda_runtime.h>
#include <cuda_bf16.h>

// Problem constants (fixed by the reference)
#define N_NODES 8192
#define K_NB    64
#define F_DIM   128
#define ROW_LEN 257                         // 2F+1
#define TOTAL_E (N_NODES * K_NB)            // 524288 write events
#define SAMPLES_ELEMS ((long long)TOTAL_E * ROW_LEN)
#define TILE_R   128                        // rows per fill tile
#define N_TILES  (N_NODES / TILE_R)         // 64
#define CAP      16                         // per-(col,tile) bucket cap (Poisson(1))
#define NB       (N_NODES * N_TILES)        // 524288 micro-buckets
#define FILL_BLKS 512                       // 64 row-tiles * 8 col-blocks (4 cols/thread)
#define RB_W     132                        // rowbuf stride (128 vals + sw + pad)

// Scratch (allocation-free __device__ globals; zero-initialized at load).
// Invariant: g_cnt is all-zero on entry to scatter — restored each run by
// fill_kernel (the unique final reader of each bucket) resetting it.
__device__ int g_cnt[NB];                   // 2 MB  events per (col,tile)
__device__ int g_bkt[NB * CAP];             // 32 MB timestamps
__device__ int g_carry[NB];                 // 2 MB  max ts in tiles < t (-1 if none)

// ---------------------------------------------------------------------------
// Scatter each event ts = r*K+j into micro-bucket (col, r/TILE_R).
__global__ void scatter_kernel(const int* __restrict__ idx_in) {
    const int e = blockIdx.x * blockDim.x + threadIdx.x;
    const int r = e >> 6;
    const int j = e & (K_NB - 1);
    const int c = (j < K_NB - 1) ? __ldg(&idx_in[r * (K_NB - 1) + j]) : r;
    const int bid = c * N_TILES + (r >> 7);
    const int p = atomicAdd(&g_cnt[bid], 1);
    if (p < CAP) g_bkt[bid * CAP + p] = e;
}

// Warp per column: sort each micro-bucket (mean 1 event), then exclusive
// prefix-max of bucket maxima over the 64 tiles -> carry-in timestamps.
__device__ __forceinline__ int sort_bucket(int b) {
    int m = g_cnt[b]; if (m > CAP) m = CAP;
    int* __restrict__ a = &g_bkt[b * CAP];
    for (int i = 1; i < m; i++) {
        int v = a[i], j = i - 1;
        while (j >= 0 && a[j] > v) { a[j + 1] = a[j]; j--; }
        a[j + 1] = v;
    }
    return (m > 0) ? a[m - 1] : -1;          // bucket max ts (sorted => last)
}

__global__ void sortcarry_kernel() {
    const int c    = blockIdx.x * 8 + (threadIdx.x >> 5);
    const int lane = threadIdx.x & 31;
    const int b0   = c * N_TILES + 2 * lane;
    const int bmax0 = sort_bucket(b0);
    const int bmax1 = sort_bucket(b0 + 1);
    int x = max(bmax0, bmax1);
    #pragma unroll
    for (int d = 1; d < 32; d <<= 1) {
        int y = __shfl_up_sync(0xffffffffu, x, d);
        if (lane >= d) x = max(x, y);
    }
    int P = __shfl_up_sync(0xffffffffu, x, 1);
    if (lane == 0) P = -1;
    g_carry[b0]     = P;
    g_carry[b0 + 1] = max(P, bmax0);
}

// ---------------------------------------------------------------------------
// adj forward-fill: thread owns 4 adjacent columns within one row tile.
// (R8/R10 body; also resets g_cnt for the next graph replay.)
// ---------------------------------------------------------------------------
__global__ void __launch_bounds__(256, 8) fill_kernel(
    const float* __restrict__ edge, float* __restrict__ out)
{
    float* __restrict__ adj = out + SAMPLES_ELEMS;
    const int b  = blockIdx.x;
    const int tt = b >> 3;                       // tile index (0..63)
    const int r0 = tt * TILE_R;
    const int c0 = (b & 7) * 1024 + threadIdx.x * 4;

    int   pos[4], m[4], nxt[4], bas[4];
    float val[4];
    #pragma unroll
    for (int u = 0; u < 4; u++) {
        const int bid = (c0 + u) * N_TILES + tt;
        int mm = g_cnt[bid]; if (mm > CAP) mm = CAP;
        g_cnt[bid] = 0;                          // consumer reset (sole owner)
        m[u] = mm; bas[u] = bid * CAP; pos[u] = 0;
        nxt[u] = (mm > 0) ? __ldg(&g_bkt[bid * CAP]) : 0x7fffffff;
        const int cts = __ldg(&g_carry[bid]);
        val[u] = (cts >= 0) ? __ldg(&edge[cts]) : 0.0f;
    }

    long long off = (long long)r0 * N_NODES + c0;
    for (int i = 0; i < TILE_R; i++) {
        const int lim = (r0 + i + 1) * K_NB;     // events with row <= r0+i
        float4 v;
        #pragma unroll
        for (int u = 0; u < 4; u++) {
            while (nxt[u] < lim) {               // register compare; rare advance
                val[u] = __ldg(&edge[nxt[u]]);
                pos[u]++;
                nxt[u] = (pos[u] < m[u]) ? __ldg(&g_bkt[bas[u] + pos[u]])
                                         : 0x7fffffff;
            }
            ((float*)&v)[u] = val[u];
        }
        __stcs((float4*)(adj + off), v);         // streaming: write-once data
        off += N_NODES;
    }
}

// ---------------------------------------------------------------------------
// samples gather-concat: one node per block. Neighbor rows are STAGED into
// smem with coalesced LDG.128 (two 32-row passes), so the hot loop is pure
// predicated LDS.32 + STG.128 — no selects, no scattered gathers.
// ---------------------------------------------------------------------------
__global__ void __launch_bounds__(256, 8) samples_kernel(
    const float* __restrict__ emb,
    const float* __restrict__ sw,
    const int*   __restrict__ idx_in,
    float* __restrict__ out)
{
    const int i = blockIdx.x;
    const int t = threadIdx.x;

    __shared__ float node_row[F_DIM];
    __shared__ int   nidx[K_NB];
    __shared__ float rowbuf[32 * RB_W];          // 32 rows: 128 vals + sw@128
    if (t < F_DIM) node_row[t] = __ldg(&emb[i * F_DIM + t]);
    if (t < K_NB)  nidx[t] = (t < K_NB - 1) ? __ldg(&idx_in[i * (K_NB - 1) + t]) : i;
    __syncthreads();

    // Per-thread fixed classification (float4 q within a 4-row group; the
    // pattern repeats every 257 float4s = 4 sample rows).
    // Thread t covers q = t; thread 0 also covers q = 256.
    for (int h = 0; h < 2; h++) {                // two 32-row halves
        // ---- stage 32 neighbor rows: coalesced, conflict-free ------------
        #pragma unroll
        for (int p = 0; p < 4; p++) {
            const int idx = t + 256 * p;         // 1024 float4s
            const int r   = idx >> 5;
            const int f4  = idx & 31;
            const int c   = nidx[h * 32 + r];
            const float4 v = __ldg((const float4*)(emb + c * F_DIM) + f4);
            *(float4*)&rowbuf[r * RB_W + f4 * 4] = v;
        }
        if (t < 32) rowbuf[t * RB_W + F_DIM] = __ldg(&sw[nidx[h * 32 + t]]);
        __syncthreads();

        float* __restrict__ obase = out + (long long)i * (K_NB * ROW_LEN) + h * (32 * ROW_LEN);

        const int nq = (t == 0) ? 2 : 1;
        for (int s = 0; s < nq; s++) {
            const int q = (s == 0) ? t : 256;
            bool  isn[4];
            int   a[4];
            float nodev[4];
            #pragma unroll
            for (int l = 0; l < 4; l++) {
                const int ff  = 4 * q + l;
                const int rw  = (ff >= 257) + (ff >= 514) + (ff >= 771);
                const int col = ff - rw * ROW_LEN;
                isn[l]   = (col < F_DIM);
                nodev[l] = isn[l] ? node_row[col] : 0.0f;
                a[l]     = isn[l] ? 0 : (rw * RB_W + (col - F_DIM)); // col 256 -> slot 128
            }
            #pragma unroll
            for (int k = 0; k < 8; k++) {        // rows rw, rw+4, ..., rw+28
                float4 v;
                #pragma unroll
                for (int l = 0; l < 4; l++) {
                    ((float*)&v)[l] = isn[l] ? nodev[l]
                                             : rowbuf[a[l] + k * 4 * RB_W];
                }
                __stcs((float4*)(obase + 4 * (q + 257 * k)), v);
            }
        }
        __syncthreads();
    }
}

// ---------------------------------------------------------------------------
// Fork/join: samples (no deps) runs on the launch stream while the adj
// pipeline (scatter -> sortcarry -> fill) runs on a side stream. Stream and
// events are created lazily on the FIRST call (the harness's correctness run,
// before graph capture), so no resource creation occurs during capture.
// ---------------------------------------------------------------------------
extern "C" void kernel_launch(void* const* d_in, const int* in_sizes, int n_in,
                              void* d_out, int out_size) {
    const float* emb      = (const float*)d_in[0];   // [8192, 128]
    const float* sw       = (const float*)d_in[1];   // [8192]
    const int*   idx_in   = (const int*)  d_in[2];   // [8192, 63]
    const float* edge_out = (const float*)d_in[3];   // [8192, 64]
    float* out = (float*)d_out;

    static cudaStream_t side = nullptr;
    static cudaEvent_t  ev_fork = nullptr, ev_join = nullptr;
    if (side == nullptr) {
        cudaStreamCreateWithFlags(&side, cudaStreamNonBlocking);
        cudaEventCreateWithFlags(&ev_fork, cudaEventDisableTiming);
        cudaEventCreateWithFlags(&ev_join, cudaEventDisableTiming);
    }

    // fork: side stream branches off the launch stream
    cudaEventRecord(ev_fork, 0);
    cudaStreamWaitEvent(side, ev_fork, 0);

    // adj pipeline on side stream (268 MB of the output)
    scatter_kernel  <<<TOTAL_E / 256, 256, 0, side>>>(idx_in);
    sortcarry_kernel<<<N_NODES / 8, 256, 0, side>>>();
    fill_kernel     <<<FILL_BLKS, 256, 0, side>>>(edge_out, out);
    cudaEventRecord(ev_join, side);

    // samples on the launch stream, concurrent with the side pipeline (539 MB)
    samples_kernel<<<N_NODES, 256>>>(emb, sw, idx_in, out);

    // join: launch stream waits for the side pipeline
    cudaStreamWaitEvent(0, ev_join, 0);
}

// round 13
// speedup vs baseline: 1.6658x; 1.0443x over previous
#include <cuda_runtime.h>
#include <cuda_bf16.h>

// Problem constants (fixed by the reference)
#define N_NODES 8192
#define K_NB    64
#define F_DIM   128
#define ROW_LEN 257                         // 2F+1
#define TOTAL_E (N_NODES * K_NB)            // 524288 write events
#define SAMPLES_ELEMS ((long long)TOTAL_E * ROW_LEN)
#define TILE_R   128                        // rows per fill tile
#define N_TILES  (N_NODES / TILE_R)         // 64
#define CAP      16                         // per-(col,tile) bucket cap (Poisson(1))
#define NB       (N_NODES * N_TILES)        // 524288 micro-buckets
#define FILL_BLKS 512                       // 64 row-tiles * 8 col-blocks (4 cols/thread)
#define RB_W     132                        // rowbuf stride (perm range 0..131)

// Bank-conflict-killing permutation: slot s (0..128) -> (s>>2) + (s&3)*33.
// Lane-stride-4 reads in s become lane-stride-1 in the permuted address.
#define PERM(s) (((s) >> 2) + ((s) & 3) * 33)

// Scratch (allocation-free __device__ globals; zero-initialized at load).
// Invariant: g_cnt is all-zero on entry to scatter — restored each run by
// fill_kernel (the unique final reader of each bucket) resetting it.
__device__ int g_cnt[NB];                   // 2 MB  events per (col,tile)
__device__ int g_bkt[NB * CAP];             // 32 MB timestamps
__device__ int g_carry[NB];                 // 2 MB  max ts in tiles < t (-1 if none)

// ---------------------------------------------------------------------------
// Scatter each event ts = r*K+j into micro-bucket (col, r/TILE_R).
__global__ void scatter_kernel(const int* __restrict__ idx_in) {
    const int e = blockIdx.x * blockDim.x + threadIdx.x;
    const int r = e >> 6;
    const int j = e & (K_NB - 1);
    const int c = (j < K_NB - 1) ? __ldg(&idx_in[r * (K_NB - 1) + j]) : r;
    const int bid = c * N_TILES + (r >> 7);
    const int p = atomicAdd(&g_cnt[bid], 1);
    if (p < CAP) g_bkt[bid * CAP + p] = e;
}

// Warp per column: sort each micro-bucket (mean 1 event), then exclusive
// prefix-max of bucket maxima over the 64 tiles -> carry-in timestamps.
__device__ __forceinline__ int sort_bucket(int b) {
    int m = g_cnt[b]; if (m > CAP) m = CAP;
    int* __restrict__ a = &g_bkt[b * CAP];
    for (int i = 1; i < m; i++) {
        int v = a[i], j = i - 1;
        while (j >= 0 && a[j] > v) { a[j + 1] = a[j]; j--; }
        a[j + 1] = v;
    }
    return (m > 0) ? a[m - 1] : -1;          // bucket max ts (sorted => last)
}

__global__ void sortcarry_kernel() {
    const int c    = blockIdx.x * 8 + (threadIdx.x >> 5);
    const int lane = threadIdx.x & 31;
    const int b0   = c * N_TILES + 2 * lane;
    const int bmax0 = sort_bucket(b0);
    const int bmax1 = sort_bucket(b0 + 1);
    int x = max(bmax0, bmax1);
    #pragma unroll
    for (int d = 1; d < 32; d <<= 1) {
        int y = __shfl_up_sync(0xffffffffu, x, d);
        if (lane >= d) x = max(x, y);
    }
    int P = __shfl_up_sync(0xffffffffu, x, 1);
    if (lane == 0) P = -1;
    g_carry[b0]     = P;
    g_carry[b0 + 1] = max(P, bmax0);
}

// ---------------------------------------------------------------------------
// adj forward-fill: thread owns 4 adjacent columns within one row tile.
// (R8/R10 body; also resets g_cnt for the next graph replay.)
// ---------------------------------------------------------------------------
__global__ void __launch_bounds__(256, 8) fill_kernel(
    const float* __restrict__ edge, float* __restrict__ out)
{
    float* __restrict__ adj = out + SAMPLES_ELEMS;
    const int b  = blockIdx.x;
    const int tt = b >> 3;                       // tile index (0..63)
    const int r0 = tt * TILE_R;
    const int c0 = (b & 7) * 1024 + threadIdx.x * 4;

    int   pos[4], m[4], nxt[4], bas[4];
    float val[4];
    #pragma unroll
    for (int u = 0; u < 4; u++) {
        const int bid = (c0 + u) * N_TILES + tt;
        int mm = g_cnt[bid]; if (mm > CAP) mm = CAP;
        g_cnt[bid] = 0;                          // consumer reset (sole owner)
        m[u] = mm; bas[u] = bid * CAP; pos[u] = 0;
        nxt[u] = (mm > 0) ? __ldg(&g_bkt[bid * CAP]) : 0x7fffffff;
        const int cts = __ldg(&g_carry[bid]);
        val[u] = (cts >= 0) ? __ldg(&edge[cts]) : 0.0f;
    }

    long long off = (long long)r0 * N_NODES + c0;
    for (int i = 0; i < TILE_R; i++) {
        const int lim = (r0 + i + 1) * K_NB;     // events with row <= r0+i
        float4 v;
        #pragma unroll
        for (int u = 0; u < 4; u++) {
            while (nxt[u] < lim) {               // register compare; rare advance
                val[u] = __ldg(&edge[nxt[u]]);
                pos[u]++;
                nxt[u] = (pos[u] < m[u]) ? __ldg(&g_bkt[bas[u] + pos[u]])
                                         : 0x7fffffff;
            }
            ((float*)&v)[u] = val[u];
        }
        __stcs((float4*)(adj + off), v);         // streaming: write-once data
        off += N_NODES;
    }
}

// ---------------------------------------------------------------------------
// samples gather-concat: one node per block. Neighbor rows staged into smem
// (coalesced LDG.128); smem layout PERMUTED so the hot-loop's lane-stride-4
// scalar reads become lane-stride-1 -> zero bank conflicts.
// ---------------------------------------------------------------------------
__global__ void __launch_bounds__(256, 8) samples_kernel(
    const float* __restrict__ emb,
    const float* __restrict__ sw,
    const int*   __restrict__ idx_in,
    float* __restrict__ out)
{
    const int i = blockIdx.x;
    const int t = threadIdx.x;

    __shared__ float node_row[RB_W];             // permuted node values
    __shared__ int   nidx[K_NB];
    __shared__ float rowbuf[32 * RB_W];          // 32 rows, permuted; sw@PERM(128)=32
    if (t < F_DIM) node_row[PERM(t)] = __ldg(&emb[i * F_DIM + t]);
    if (t < K_NB)  nidx[t] = (t < K_NB - 1) ? __ldg(&idx_in[i * (K_NB - 1) + t]) : i;
    __syncthreads();

    for (int h = 0; h < 2; h++) {                // two 32-row halves
        // ---- stage 32 neighbor rows: coalesced LDG.128, permuted STS.32 ---
        #pragma unroll
        for (int p = 0; p < 4; p++) {
            const int idx = t + 256 * p;         // 1024 float4s
            const int r   = idx >> 5;
            const int f4  = idx & 31;            // slot base = 4*f4
            const int c   = nidx[h * 32 + r];
            const float4 v = __ldg((const float4*)(emb + c * F_DIM) + f4);
            float* __restrict__ rb = &rowbuf[r * RB_W + f4]; // PERM(4*f4+j)=f4+33j
            rb[0]  = v.x;  rb[33] = v.y;  rb[66] = v.z;  rb[99] = v.w;
        }
        if (t < 32) rowbuf[t * RB_W + 32] = __ldg(&sw[nidx[h * 32 + t]]);
        __syncthreads();

        float* __restrict__ obase = out + (long long)i * (K_NB * ROW_LEN) + h * (32 * ROW_LEN);

        const int nq = (t == 0) ? 2 : 1;         // thread 0 also covers q=256
        for (int s = 0; s < nq; s++) {
            const int q = (s == 0) ? t : 256;
            // Fixed per-lane classification (pattern repeats every 4 rows).
            bool  isn[4];
            int   a[4];
            float nodev[4];
            #pragma unroll
            for (int l = 0; l < 4; l++) {
                const int ff  = 4 * q + l;
                const int rw  = (ff >= 257) + (ff >= 514) + (ff >= 771);
                const int col = ff - rw * ROW_LEN;
                isn[l]   = (col < F_DIM);
                nodev[l] = isn[l] ? node_row[PERM(col)] : 0.0f;
                a[l]     = isn[l] ? 0 : (rw * RB_W + PERM(col - F_DIM)); // col 256 -> sw
            }
            #pragma unroll
            for (int k = 0; k < 8; k++) {        // rows rw, rw+4, ..., rw+28
                float4 v;
                #pragma unroll
                for (int l = 0; l < 4; l++) {
                    ((float*)&v)[l] = isn[l] ? nodev[l]
                                             : rowbuf[a[l] + k * 4 * RB_W];
                }
                __stcs((float4*)(obase + 4 * (q + 257 * k)), v);
            }
        }
        __syncthreads();
    }
}

// ---------------------------------------------------------------------------
// Fork/join: samples (no deps) runs on the launch stream while the adj
// pipeline (scatter -> sortcarry -> fill) runs on a side stream. Stream and
// events are created lazily on the FIRST call (the harness's correctness run,
// before graph capture), so no resource creation occurs during capture.
// ---------------------------------------------------------------------------
extern "C" void kernel_launch(void* const* d_in, const int* in_sizes, int n_in,
                              void* d_out, int out_size) {
    const float* emb      = (const float*)d_in[0];   // [8192, 128]
    const float* sw       = (const float*)d_in[1];   // [8192]
    const int*   idx_in   = (const int*)  d_in[2];   // [8192, 63]
    const float* edge_out = (const float*)d_in[3];   // [8192, 64]
    float* out = (float*)d_out;

    static cudaStream_t side = nullptr;
    static cudaEvent_t  ev_fork = nullptr, ev_join = nullptr;
    if (side == nullptr) {
        cudaStreamCreateWithFlags(&side, cudaStreamNonBlocking);
        cudaEventCreateWithFlags(&ev_fork, cudaEventDisableTiming);
        cudaEventCreateWithFlags(&ev_join, cudaEventDisableTiming);
    }

    // fork: side stream branches off the launch stream
    cudaEventRecord(ev_fork, 0);
    cudaStreamWaitEvent(side, ev_fork, 0);

    // adj pipeline on side stream (268 MB of the output)
    scatter_kernel  <<<TOTAL_E / 256, 256, 0, side>>>(idx_in);
    sortcarry_kernel<<<N_NODES / 8, 256, 0, side>>>();
    fill_kernel     <<<FILL_BLKS, 256, 0, side>>>(edge_out, out);
    cudaEventRecord(ev_join, side);

    // samples on the launch stream, concurrent with the side pipeline (539 MB)
    samples_kernel<<<N_NODES, 256>>>(emb, sw, idx_in, out);

    // join: launch stream waits for the side pipeline
    cudaStreamWaitEvent(0, ev_join, 0);
}

// round 14
// speedup vs baseline: 1.6760x; 1.0061x over previous
#include <cuda_runtime.h>
#include <cuda_bf16.h>

// Problem constants (fixed by the reference)
#define N_NODES 8192
#define K_NB    64
#define F_DIM   128
#define ROW_LEN 257                         // 2F+1
#define TOTAL_E (N_NODES * K_NB)            // 524288 write events
#define SAMPLES_ELEMS ((long long)TOTAL_E * ROW_LEN)
#define TILE_R   128                        // rows per fill tile
#define N_TILES  (N_NODES / TILE_R)         // 64
#define CAP      16                         // per-(col,tile) bucket cap (Poisson(1))
#define NB       (N_NODES * N_TILES)        // 524288 micro-buckets
#define FILL_BLKS 512                       // 64 row-tiles * 8 col-blocks (4 cols/thread)
#define RB_W     132                        // rowbuf stride (perm range 0..131)
#define HEAD     2048                       // samples head nodes (overlap the prelude)

// Bank-conflict-killing permutation: slot s (0..128) -> (s>>2) + (s&3)*33.
#define PERM(s) (((s) >> 2) + ((s) & 3) * 33)

// Scratch (allocation-free __device__ globals; zero-initialized at load).
// Invariant: g_cnt is all-zero on entry to scatter — restored each run by
// the fill path (unique final reader of each bucket) resetting it.
__device__ int g_cnt[NB];                   // 2 MB  events per (col,tile)
__device__ int g_bkt[NB * CAP];             // 32 MB timestamps
__device__ int g_carry[NB];                 // 2 MB  max ts in tiles < t (-1 if none)

// ---------------------------------------------------------------------------
// Scatter each event ts = r*K+j into micro-bucket (col, r/TILE_R).
__global__ void scatter_kernel(const int* __restrict__ idx_in) {
    const int e = blockIdx.x * blockDim.x + threadIdx.x;
    const int r = e >> 6;
    const int j = e & (K_NB - 1);
    const int c = (j < K_NB - 1) ? __ldg(&idx_in[r * (K_NB - 1) + j]) : r;
    const int bid = c * N_TILES + (r >> 7);
    const int p = atomicAdd(&g_cnt[bid], 1);
    if (p < CAP) g_bkt[bid * CAP + p] = e;
}

// Warp per column: sort each micro-bucket (mean 1 event), then exclusive
// prefix-max of bucket maxima over the 64 tiles -> carry-in timestamps.
__device__ __forceinline__ int sort_bucket(int b) {
    int m = g_cnt[b]; if (m > CAP) m = CAP;
    int* __restrict__ a = &g_bkt[b * CAP];
    for (int i = 1; i < m; i++) {
        int v = a[i], j = i - 1;
        while (j >= 0 && a[j] > v) { a[j + 1] = a[j]; j--; }
        a[j + 1] = v;
    }
    return (m > 0) ? a[m - 1] : -1;          // bucket max ts (sorted => last)
}

__global__ void sortcarry_kernel() {
    const int c    = blockIdx.x * 8 + (threadIdx.x >> 5);
    const int lane = threadIdx.x & 31;
    const int b0   = c * N_TILES + 2 * lane;
    const int bmax0 = sort_bucket(b0);
    const int bmax1 = sort_bucket(b0 + 1);
    int x = max(bmax0, bmax1);
    #pragma unroll
    for (int d = 1; d < 32; d <<= 1) {
        int y = __shfl_up_sync(0xffffffffu, x, d);
        if (lane >= d) x = max(x, y);
    }
    int P = __shfl_up_sync(0xffffffffu, x, 1);
    if (lane == 0) P = -1;
    g_carry[b0]     = P;
    g_carry[b0 + 1] = max(P, bmax0);
}

// ---------------------------------------------------------------------------
// adj forward-fill body (R13-measured): thread owns 4 adjacent columns.
// Also resets g_cnt for the next graph replay.
// ---------------------------------------------------------------------------
__device__ __forceinline__ void fill_body(
    const float* __restrict__ edge, float* __restrict__ out, int b, int t)
{
    float* __restrict__ adj = out + SAMPLES_ELEMS;
    const int tt = b >> 3;                       // tile index (0..63)
    const int r0 = tt * TILE_R;
    const int c0 = (b & 7) * 1024 + t * 4;

    int   pos[4], m[4], nxt[4], bas[4];
    float val[4];
    #pragma unroll
    for (int u = 0; u < 4; u++) {
        const int bid = (c0 + u) * N_TILES + tt;
        int mm = g_cnt[bid]; if (mm > CAP) mm = CAP;
        g_cnt[bid] = 0;                          // consumer reset (sole owner)
        m[u] = mm; bas[u] = bid * CAP; pos[u] = 0;
        nxt[u] = (mm > 0) ? __ldg(&g_bkt[bid * CAP]) : 0x7fffffff;
        const int cts = __ldg(&g_carry[bid]);
        val[u] = (cts >= 0) ? __ldg(&edge[cts]) : 0.0f;
    }

    long long off = (long long)r0 * N_NODES + c0;
    for (int i = 0; i < TILE_R; i++) {
        const int lim = (r0 + i + 1) * K_NB;     // events with row <= r0+i
        float4 v;
        #pragma unroll
        for (int u = 0; u < 4; u++) {
            while (nxt[u] < lim) {               // register compare; rare advance
                val[u] = __ldg(&edge[nxt[u]]);
                pos[u]++;
                nxt[u] = (pos[u] < m[u]) ? __ldg(&g_bkt[bas[u] + pos[u]])
                                         : 0x7fffffff;
            }
            ((float*)&v)[u] = val[u];
        }
        __stcs((float4*)(adj + off), v);         // streaming: write-once data
        off += N_NODES;
    }
}

// ---------------------------------------------------------------------------
// samples body (R13-measured): staged neighbor rows, PERM smem (no conflicts).
// ---------------------------------------------------------------------------
__device__ __forceinline__ void samples_body(
    const float* __restrict__ emb,
    const float* __restrict__ sw,
    const int*   __restrict__ idx_in,
    float* __restrict__ out, int i, int t)
{
    __shared__ float node_row[RB_W];             // permuted node values
    __shared__ int   nidx[K_NB];
    __shared__ float rowbuf[32 * RB_W];          // 32 rows, permuted; sw@PERM(128)=32
    if (t < F_DIM) node_row[PERM(t)] = __ldg(&emb[i * F_DIM + t]);
    if (t < K_NB)  nidx[t] = (t < K_NB - 1) ? __ldg(&idx_in[i * (K_NB - 1) + t]) : i;
    __syncthreads();

    for (int h = 0; h < 2; h++) {                // two 32-row halves
        // ---- stage 32 neighbor rows: coalesced LDG.128, permuted STS.32 ---
        #pragma unroll
        for (int p = 0; p < 4; p++) {
            const int idx = t + 256 * p;         // 1024 float4s
            const int r   = idx >> 5;
            const int f4  = idx & 31;            // slot base = 4*f4
            const int c   = nidx[h * 32 + r];
            const float4 v = __ldg((const float4*)(emb + c * F_DIM) + f4);
            float* __restrict__ rb = &rowbuf[r * RB_W + f4]; // PERM(4*f4+j)=f4+33j
            rb[0]  = v.x;  rb[33] = v.y;  rb[66] = v.z;  rb[99] = v.w;
        }
        if (t < 32) rowbuf[t * RB_W + 32] = __ldg(&sw[nidx[h * 32 + t]]);
        __syncthreads();

        float* __restrict__ obase = out + (long long)i * (K_NB * ROW_LEN) + h * (32 * ROW_LEN);

        const int nq = (t == 0) ? 2 : 1;         // thread 0 also covers q=256
        for (int s = 0; s < nq; s++) {
            const int q = (s == 0) ? t : 256;
            bool  isn[4];
            int   a[4];
            float nodev[4];
            #pragma unroll
            for (int l = 0; l < 4; l++) {
                const int ff  = 4 * q + l;
                const int rw  = (ff >= 257) + (ff >= 514) + (ff >= 771);
                const int col = ff - rw * ROW_LEN;
                isn[l]   = (col < F_DIM);
                nodev[l] = isn[l] ? node_row[PERM(col)] : 0.0f;
                a[l]     = isn[l] ? 0 : (rw * RB_W + PERM(col - F_DIM)); // col 256 -> sw
            }
            #pragma unroll
            for (int k = 0; k < 8; k++) {        // rows rw, rw+4, ..., rw+28
                float4 v;
                #pragma unroll
                for (int l = 0; l < 4; l++) {
                    ((float*)&v)[l] = isn[l] ? nodev[l]
                                             : rowbuf[a[l] + k * 4 * RB_W];
                }
                __stcs((float4*)(obase + 4 * (q + 257 * k)), v);
            }
        }
        __syncthreads();
    }
}

// Head: samples for nodes [0, HEAD) — no prelude dependency, overlaps it.
__global__ void __launch_bounds__(256, 8) samples_head_kernel(
    const float* __restrict__ emb, const float* __restrict__ sw,
    const int* __restrict__ idx_in, float* __restrict__ out)
{
    samples_body(emb, sw, idx_in, out, blockIdx.x, threadIdx.x);
}

// Tail: fill (blockIdx < FILL_BLKS) + samples for nodes [HEAD, N) in ONE grid
// so both block types are co-resident and share DRAM bandwidth.
__global__ void __launch_bounds__(256, 8) fused_tail_kernel(
    const float* __restrict__ emb, const float* __restrict__ sw,
    const int* __restrict__ idx_in, const float* __restrict__ edge,
    float* __restrict__ out)
{
    if (blockIdx.x < FILL_BLKS)
        fill_body(edge, out, blockIdx.x, threadIdx.x);
    else
        samples_body(emb, sw, idx_in, out, HEAD + blockIdx.x - FILL_BLKS, threadIdx.x);
}

// ---------------------------------------------------------------------------
// Schedule:  main:  samples_head ─────────────┐
//            side:  scatter → sortcarry ──────┴→ main: fused_tail
// Side stream is highest-priority so its (small) kernels co-run with the head.
// Stream/events created lazily on the FIRST call (the harness's correctness
// run, before graph capture) — no resource creation during capture.
// ---------------------------------------------------------------------------
extern "C" void kernel_launch(void* const* d_in, const int* in_sizes, int n_in,
                              void* d_out, int out_size) {
    const float* emb      = (const float*)d_in[0];   // [8192, 128]
    const float* sw       = (const float*)d_in[1];   // [8192]
    const int*   idx_in   = (const int*)  d_in[2];   // [8192, 63]
    const float* edge_out = (const float*)d_in[3];   // [8192, 64]
    float* out = (float*)d_out;

    static cudaStream_t side = nullptr;
    static cudaEvent_t  ev_fork = nullptr, ev_join = nullptr;
    if (side == nullptr) {
        int lo, hi;                                   // hi = greatest priority
        cudaDeviceGetStreamPriorityRange(&lo, &hi);
        cudaStreamCreateWithPriority(&side, cudaStreamNonBlocking, hi);
        cudaEventCreateWithFlags(&ev_fork, cudaEventDisableTiming);
        cudaEventCreateWithFlags(&ev_join, cudaEventDisableTiming);
    }

    // fork: side stream branches off the launch stream
    cudaEventRecord(ev_fork, 0);
    cudaStreamWaitEvent(side, ev_fork, 0);

    // adj prelude on high-priority side stream (ready at fork time)
    scatter_kernel  <<<TOTAL_E / 256, 256, 0, side>>>(idx_in);
    sortcarry_kernel<<<N_NODES / 8, 256, 0, side>>>();
    cudaEventRecord(ev_join, side);

    // samples head on the launch stream, concurrent with the prelude
    samples_head_kernel<<<HEAD, 256>>>(emb, sw, idx_in, out);

    // join, then the fused tail (fill + remaining samples, co-resident)
    cudaStreamWaitEvent(0, ev_join, 0);
    fused_tail_kernel<<<FILL_BLKS + (N_NODES - HEAD), 256>>>(emb, sw, idx_in, edge_out, out);
}